// round 2
// baseline (speedup 1.0000x reference)
#include <cuda_runtime.h>
#include <math.h>

#define NT 8192          // total tiles: bs(8) * n(32) * n(32)
#define NSM 148          // sm_100a B200

static __device__ float g_P[64 * 256];   // P[pair][c], pair = m1*8+m2

// ---------------------------------------------------------------------------
// Kernel 1: P[p][c] = sum_d pe[p][d] * W[c][d]
// pe[p][2k] = sin(p * div[k]), pe[p][2k+1] = cos(p * div[k]),
// div[k] = exp(-k * ln(10000)/32)
// ---------------------------------------------------------------------------
__global__ void compute_P_kernel(const float* __restrict__ W) {
    __shared__ float pe_row[64];
    int p = blockIdx.x;
    int c = threadIdx.x;
    if (c < 32) {
        float div = expf(-(float)c * 0.28782313662425572f);  // ln(1e4)/32
        float ang = (float)p * div;
        pe_row[2 * c]     = sinf(ang);
        pe_row[2 * c + 1] = cosf(ang);
    }
    __syncthreads();
    const float* wr = W + c * 64;
    float acc = 0.f;
#pragma unroll
    for (int d = 0; d < 64; ++d) acc += pe_row[d] * wr[d];
    g_P[p * 256 + c] = acc;
}

// ---------------------------------------------------------------------------
// Kernel 2: persistent broadcast+scale kernel.
// SMEM layout (floats):
//   Wt   [0 .. 16448)    : W transposed, padded stride 257 (conflict-free)
//   P    [16448 .. 32832): P[pair*256 + c]
//   Asm  [32832 .. 33088): a[c] for current tile
//   Esm  [33088 .. 33216): double-buffered E row (2 x 64)
//   M2   [33216 .. 33232): double-buffered mask2 (2 x 8)
//   M1   [33232 .. 33234): double-buffered mask1 (2 x 1)
// ---------------------------------------------------------------------------
__global__ void __launch_bounds__(256, 1) etoc_main_kernel(
    const float* __restrict__ E,
    const float* __restrict__ m1g,
    const float* __restrict__ m2g,
    const float* __restrict__ Wg,
    float4* __restrict__ out4,
    int grid_stride)
{
    extern __shared__ float sm[];
    float* Wt  = sm;
    float* P   = sm + 16448;
    float* Asm = sm + 32832;
    float* Esm = sm + 33088;
    float* M2  = sm + 33216;
    float* M1  = sm + 33232;

    const int tid = threadIdx.x;

    // Stage W transposed (coalesced GMEM read; STS banks (d+c)%32 distinct)
    for (int idx = tid; idx < 16384; idx += 256) {
        int c = idx >> 6, d = idx & 63;
        Wt[d * 257 + c] = Wg[idx];
    }
    // Stage P (coalesced, conflict-free)
    for (int idx = tid; idx < 16384; idx += 256) P[idx] = g_P[idx];

    // Preload first tile's E row + masks into buffer 0
    {
        int t0 = blockIdx.x;
        int b = t0 >> 10, rem = t0 & 1023, i1 = rem >> 5, j1 = rem & 31;
        if (tid < 64) {
            Esm[tid] = E[((b * 32 + i1) * 32 + j1) * 64 + tid];
        } else if (tid < 72) {
            int m2i = tid - 64;
            M2[m2i] = m2g[b * 32 + ((j1 * 8 + m2i) & 31)];
        } else if (tid == 72) {
            M1[0] = m1g[b * 32 + i1];
        }
    }
    __syncthreads();

    const int cq  = tid & 63;   // float4 column index within 256-wide c
    const int grp = tid >> 6;   // which (m1,m2) pair group this thread serves

    int cur = 0;
    for (int t = blockIdx.x; t < NT; t += grid_stride) {
        int b = t >> 10, rem = t & 1023, i1 = rem >> 5, j1 = rem & 31;

        // GEMV: a[c] = sum_d E_row[d] * W[c][d]
        // e[d]: warp broadcast; Wt[d*257+tid]: consecutive -> conflict-free
        {
            const float* e = Esm + cur * 64;
            float acc = 0.f;
#pragma unroll
            for (int d = 0; d < 64; ++d) acc += e[d] * Wt[d * 257 + tid];
            Asm[tid] = acc;
        }
        float m1v = M1[cur];
        __syncthreads();

        // Prefetch next tile's E row + masks into the other buffer
        int tn  = t + grid_stride;
        int nxt = cur ^ 1;
        if (tn < NT) {
            int bn = tn >> 10, remn = tn & 1023, i1n = remn >> 5, j1n = remn & 31;
            if (tid < 64) {
                Esm[nxt * 64 + tid] = E[((bn * 32 + i1n) * 32 + j1n) * 64 + tid];
            } else if (tid < 72) {
                int m2i = tid - 64;
                M2[nxt * 8 + m2i] = m2g[bn * 32 + ((j1n * 8 + m2i) & 31)];
            } else if (tid == 72) {
                M1[nxt] = m1g[bn * 32 + i1n];
            }
        }

        // Write phase: 64 KB of coalesced float4 streaming stores
        float4 av = *(const float4*)(Asm + 4 * cq);
        unsigned base_i = (unsigned)(b * 256 + i1 * 8);
        unsigned jb     = (unsigned)(j1 * 8);
#pragma unroll
        for (int it = 0; it < 16; ++it) {
            int pair = it * 4 + grp;
            int m1i = pair >> 3, m2i = pair & 7;
            float  mk = m1v * M2[cur * 8 + m2i];
            float4 p4 = *(const float4*)(P + pair * 256 + 4 * cq);
            float4 v;
            v.x = mk * (av.x + p4.x);
            v.y = mk * (av.y + p4.y);
            v.z = mk * (av.z + p4.z);
            v.w = mk * (av.w + p4.w);
            unsigned idx4 = ((base_i + (unsigned)m1i) * 256u + jb + (unsigned)m2i) * 64u
                            + (unsigned)cq;
            __stcs(out4 + idx4, v);
        }

        cur = nxt;
        __syncthreads();
    }
}

// ---------------------------------------------------------------------------
// Launch
// ---------------------------------------------------------------------------
extern "C" void kernel_launch(void* const* d_in, const int* in_sizes, int n_in,
                              void* d_out, int out_size) {
    const float* E  = (const float*)d_in[0];  // (8,32,32,64)
    const float* m1 = (const float*)d_in[1];  // (8,32,1,1)
    const float* m2 = (const float*)d_in[2];  // (8,1,32,1)
    const float* W  = (const float*)d_in[3];  // (256,64)

    compute_P_kernel<<<64, 256>>>(W);

    int grid = NSM;
    size_t smem_bytes = 33234 * sizeof(float);  // ~129.8 KB
    cudaFuncSetAttribute(etoc_main_kernel,
                         cudaFuncAttributeMaxDynamicSharedMemorySize,
                         (int)smem_bytes);

    etoc_main_kernel<<<grid, 256, smem_bytes>>>(E, m1, m2, W,
                                                (float4*)d_out, grid);
}